// round 5
// baseline (speedup 1.0000x reference)
#include <cuda_runtime.h>
#include <cuda_fp16.h>
#include <cstdint>

// ---------------------------------------------------------------------------
// Problem constants
// ---------------------------------------------------------------------------
#define T_DIM 512
#define H_DIM 4096
#define I_DIM 11008

#define PITCH 80                 // bytes per 32-half smem row (conflict-free for ldmatrix)
#define NK1 (H_DIM / 32)         // 128 k-stages for gemm1
#define NK2 (I_DIM / 32)         // 344 k-stages for gemm2

#define G1_STAGE 20480           // A(10240) + Bg(5120) + Bu(5120)
#define G2_STAGE 20480           // A(10240) + B(10240)
#define G2_SMEM (3 * G2_STAGE)   // 61440, 3-stage cp.async pipeline

// Scratch (device globals — allocations are forbidden)
__device__ __align__(256) __half g_h[(size_t)T_DIM * I_DIM];     // 11.3 MB
__device__ __align__(256) __half g_wdT[(size_t)H_DIM * I_DIM];   // 90.2 MB

// ---------------------------------------------------------------------------
// sm_80-baseline PTX helpers (NO tcgen05 — harness targets compute_103 non-'a')
// ---------------------------------------------------------------------------
__device__ __forceinline__ uint32_t smem_u32(const void* p) {
    uint32_t a;
    asm("{ .reg .u64 t; cvta.to.shared.u64 t, %1; cvt.u32.u64 %0, t; }"
        : "=r"(a) : "l"(p));
    return a;
}

__device__ __forceinline__ void ldsm_x4(uint32_t* r, uint32_t addr) {
    asm volatile("ldmatrix.sync.aligned.m8n8.x4.shared.b16 {%0,%1,%2,%3}, [%4];"
                 : "=r"(r[0]), "=r"(r[1]), "=r"(r[2]), "=r"(r[3]) : "r"(addr));
}

__device__ __forceinline__ void mma16816(float* c, const uint32_t* a, const uint32_t* b) {
    asm volatile(
        "mma.sync.aligned.m16n8k16.row.col.f32.f16.f16.f32 "
        "{%0,%1,%2,%3}, {%4,%5,%6,%7}, {%8,%9}, {%0,%1,%2,%3};"
        : "+f"(c[0]), "+f"(c[1]), "+f"(c[2]), "+f"(c[3])
        : "r"(a[0]), "r"(a[1]), "r"(a[2]), "r"(a[3]), "r"(b[0]), "r"(b[1]));
}

__device__ __forceinline__ void cp16(uint32_t sdst, const void* gsrc) {
    asm volatile("cp.async.cg.shared.global [%0], [%1], 16;"
                 :: "r"(sdst), "l"(__cvta_generic_to_global(gsrc)));
}
#define CP_COMMIT() asm volatile("cp.async.commit_group;")
#define CP_WAIT0()  asm volatile("cp.async.wait_group 0;")
#define CP_WAIT1()  asm volatile("cp.async.wait_group 1;")
#define CP_WAIT2()  asm volatile("cp.async.wait_group 2;")

// ---------------------------------------------------------------------------
// Kernel 0: Wd [I,H] fp32 -> WdT [H,I] fp16, block-dequantized
// ---------------------------------------------------------------------------
__global__ __launch_bounds__(256) void transpose_dequant_kernel(
    const float* __restrict__ wd, const float* __restrict__ sd) {
    __shared__ float tile[32][33];
    int i0 = blockIdx.x * 32;
    int h0 = blockIdx.y * 32;
    float s = __ldg(&sd[(i0 >> 7) * (H_DIM / 128) + (h0 >> 7)]);
    int tx = threadIdx.x, ty = threadIdx.y;
#pragma unroll
    for (int r = ty; r < 32; r += 8)
        tile[r][tx] = wd[(size_t)(i0 + r) * H_DIM + h0 + tx];
    __syncthreads();
#pragma unroll
    for (int r = ty; r < 32; r += 8)
        g_wdT[(size_t)(h0 + r) * I_DIM + i0 + tx] = __float2half(tile[tx][r] * s);
}

// ---------------------------------------------------------------------------
// GEMM1 staging: fp32 LDG -> regs -> fused scale+cvt -> fp16 smem
// ---------------------------------------------------------------------------
__device__ __forceinline__ void ldg_g1(const float* __restrict__ x,
                                       const float* __restrict__ wg,
                                       const float* __restrict__ wu,
                                       int t0, int i0, int k0, int tid,
                                       float4* av, float4* bgv, float4* buv) {
#pragma unroll
    for (int j = 0; j < 4; j++) {
        int idx = tid + j * 256;
        int r = idx >> 3, c = idx & 7;
        av[j] = *(const float4*)(x + (size_t)(t0 + r) * H_DIM + k0 + c * 4);
    }
#pragma unroll
    for (int j = 0; j < 2; j++) {
        int idx = tid + j * 256;
        int r = idx >> 3, c = idx & 7;
        bgv[j] = *(const float4*)(wg + (size_t)(i0 + r) * H_DIM + k0 + c * 4);
        buv[j] = *(const float4*)(wu + (size_t)(i0 + r) * H_DIM + k0 + c * 4);
    }
}

__device__ __forceinline__ void sts_g1(char* st, int tid, float sgv, float suv,
                                       const float4* av, const float4* bgv,
                                       const float4* buv) {
#pragma unroll
    for (int j = 0; j < 4; j++) {
        int idx = tid + j * 256;
        int r = idx >> 3, c = idx & 7;
        __half2 h0 = __floats2half2_rn(av[j].x, av[j].y);
        __half2 h1 = __floats2half2_rn(av[j].z, av[j].w);
        uint2 w;
        w.x = *(uint32_t*)&h0; w.y = *(uint32_t*)&h1;
        *(uint2*)(st + r * PITCH + c * 8) = w;
    }
#pragma unroll
    for (int j = 0; j < 2; j++) {
        int idx = tid + j * 256;
        int r = idx >> 3, c = idx & 7;
        {
            __half2 h0 = __floats2half2_rn(bgv[j].x * sgv, bgv[j].y * sgv);
            __half2 h1 = __floats2half2_rn(bgv[j].z * sgv, bgv[j].w * sgv);
            uint2 w;
            w.x = *(uint32_t*)&h0; w.y = *(uint32_t*)&h1;
            *(uint2*)(st + 10240 + r * PITCH + c * 8) = w;
        }
        {
            __half2 h0 = __floats2half2_rn(buv[j].x * suv, buv[j].y * suv);
            __half2 h1 = __floats2half2_rn(buv[j].z * suv, buv[j].w * suv);
            uint2 w;
            w.x = *(uint32_t*)&h0; w.y = *(uint32_t*)&h1;
            *(uint2*)(st + 15360 + r * PITCH + c * 8) = w;
        }
    }
}

// ---------------------------------------------------------------------------
// Kernel 1: gate/up dual GEMM + SwiGLU -> g_h (fp16)
//   CTA: M=128 (T), N=64 (I) per matrix. 8 warps = 4(M) x 2(N). Warp: 32x32 x2.
// ---------------------------------------------------------------------------
__global__ __launch_bounds__(256) void gemm1_kernel(
    const float* __restrict__ x, const float* __restrict__ wg,
    const float* __restrict__ wu, const float* __restrict__ sg,
    const float* __restrict__ su) {
    __shared__ __align__(128) char sm[2 * G1_STAGE];
    const int tid = threadIdx.x, wid = tid >> 5, l = tid & 31;
    const int wm = wid & 3, wn = wid >> 2;
    const int t0 = blockIdx.x * 128, i0 = blockIdx.y * 64;
    const int iblk = i0 >> 7;
    const uint32_t sbase = smem_u32(sm);

    float cg[2][4][4], cu[2][4][4];
#pragma unroll
    for (int a = 0; a < 2; a++)
#pragma unroll
        for (int b = 0; b < 4; b++)
#pragma unroll
            for (int d = 0; d < 4; d++) { cg[a][b][d] = 0.f; cu[a][b][d] = 0.f; }

    float4 av[4], bgv[2], buv[2];
    ldg_g1(x, wg, wu, t0, i0, 0, tid, av, bgv, buv);
    sts_g1(sm, tid, __ldg(sg + iblk * 32), __ldg(su + iblk * 32), av, bgv, buv);
    __syncthreads();

    for (int it = 0; it < NK1; it++) {
        const int cur = it & 1;
        if (it + 1 < NK1)
            ldg_g1(x, wg, wu, t0, i0, (it + 1) * 32, tid, av, bgv, buv);

        // MMA on current stage
        const uint32_t sA = sbase + cur * G1_STAGE;
        const uint32_t sBg = sA + 10240;
        const uint32_t sBu = sA + 15360;
#pragma unroll
        for (int kk = 0; kk < 32; kk += 16) {
            uint32_t a2[2][4];
#pragma unroll
            for (int mi = 0; mi < 2; mi++)
                ldsm_x4(a2[mi], sA + (wm * 32 + mi * 16 + (l & 15)) * PITCH +
                                   (kk + ((l >> 4) << 3)) * 2);
            uint32_t bg[4][2], bu[4][2];
#pragma unroll
            for (int p = 0; p < 2; p++) {
                int m = l >> 3;
                int row = wn * 32 + (p * 2 + (m >> 1)) * 8 + (l & 7);
                uint32_t aoff = row * PITCH + (kk + (m & 1) * 8) * 2;
                uint32_t r4[4];
                ldsm_x4(r4, sBg + aoff);
                bg[p * 2][0] = r4[0]; bg[p * 2][1] = r4[1];
                bg[p * 2 + 1][0] = r4[2]; bg[p * 2 + 1][1] = r4[3];
                ldsm_x4(r4, sBu + aoff);
                bu[p * 2][0] = r4[0]; bu[p * 2][1] = r4[1];
                bu[p * 2 + 1][0] = r4[2]; bu[p * 2 + 1][1] = r4[3];
            }
#pragma unroll
            for (int mi = 0; mi < 2; mi++)
#pragma unroll
                for (int n = 0; n < 4; n++) {
                    mma16816(cg[mi][n], a2[mi], bg[n]);
                    mma16816(cu[mi][n], a2[mi], bu[n]);
                }
        }

        if (it + 1 < NK1) {
            int kb = (it + 1) >> 2;
            sts_g1(sm + ((it + 1) & 1) * G1_STAGE, tid,
                   __ldg(sg + iblk * 32 + kb), __ldg(su + iblk * 32 + kb),
                   av, bgv, buv);
        }
        __syncthreads();
    }

    // Epilogue: h = silu(gate) * up -> fp16 g_h
#pragma unroll
    for (int mi = 0; mi < 2; mi++)
#pragma unroll
        for (int n = 0; n < 4; n++) {
            int row = t0 + wm * 32 + mi * 16 + (l >> 2);
            int col = i0 + wn * 32 + n * 8 + ((l & 3) << 1);
            {
                float g0 = cg[mi][n][0], g1 = cg[mi][n][1];
                float h0 = g0 * cu[mi][n][0] / (1.0f + __expf(-g0));
                float h1 = g1 * cu[mi][n][1] / (1.0f + __expf(-g1));
                __half2 hv = __floats2half2_rn(h0, h1);
                *(uint32_t*)(&g_h[(size_t)row * I_DIM + col]) = *(uint32_t*)&hv;
            }
            {
                float g0 = cg[mi][n][2], g1 = cg[mi][n][3];
                float h0 = g0 * cu[mi][n][2] / (1.0f + __expf(-g0));
                float h1 = g1 * cu[mi][n][3] / (1.0f + __expf(-g1));
                __half2 hv = __floats2half2_rn(h0, h1);
                *(uint32_t*)(&g_h[(size_t)(row + 8) * I_DIM + col]) = *(uint32_t*)&hv;
            }
        }
}

// ---------------------------------------------------------------------------
// Kernel 2: out[T,H] = g_h[T,I] x g_wdT[H,I]^T  (fp16 in, fp32 out)
//   CTA: 128x128, BK=32, 3-stage cp.async. Warp tile 32x64.
// ---------------------------------------------------------------------------
__device__ __forceinline__ void issue_g2(uint32_t sbase, int stage, int t0, int h0,
                                         int k0, int tid) {
    uint32_t sA = sbase + stage * G2_STAGE;
    uint32_t sB = sA + 10240;
#pragma unroll
    for (int j = 0; j < 2; j++) {
        int idx = tid + j * 256;
        int r = idx >> 2, c = idx & 3;
        cp16(sA + r * PITCH + c * 16, &g_h[(size_t)(t0 + r) * I_DIM + k0 + c * 8]);
    }
#pragma unroll
    for (int j = 0; j < 2; j++) {
        int idx = tid + j * 256;
        int r = idx >> 2, c = idx & 3;
        cp16(sB + r * PITCH + c * 16, &g_wdT[(size_t)(h0 + r) * I_DIM + k0 + c * 8]);
    }
    CP_COMMIT();
}

__global__ __launch_bounds__(256) void gemm2_kernel(float* __restrict__ out) {
    extern __shared__ __align__(128) char sm2[];
    const int tid = threadIdx.x, wid = tid >> 5, l = tid & 31;
    const int wm = wid & 3, wn = wid >> 2;
    const int t0 = blockIdx.x * 128, h0 = blockIdx.y * 128;
    const uint32_t sbase = smem_u32(sm2);

    float c[2][8][4];
#pragma unroll
    for (int a = 0; a < 2; a++)
#pragma unroll
        for (int b = 0; b < 8; b++)
#pragma unroll
            for (int d = 0; d < 4; d++) c[a][b][d] = 0.f;

    issue_g2(sbase, 0, t0, h0, 0, tid);
    issue_g2(sbase, 1, t0, h0, 32, tid);

    for (int it = 0; it < NK2; it++) {
        if (it + 2 < NK2) {
            issue_g2(sbase, (it + 2) % 3, t0, h0, (it + 2) * 32, tid);
            CP_WAIT2();
        } else if (it + 1 < NK2) {
            CP_WAIT1();
        } else {
            CP_WAIT0();
        }
        __syncthreads();

        const uint32_t sA = sbase + (it % 3) * G2_STAGE;
        const uint32_t sB = sA + 10240;
#pragma unroll
        for (int kk = 0; kk < 32; kk += 16) {
            uint32_t a2[2][4];
#pragma unroll
            for (int mi = 0; mi < 2; mi++)
                ldsm_x4(a2[mi], sA + (wm * 32 + mi * 16 + (l & 15)) * PITCH +
                                   (kk + ((l >> 4) << 3)) * 2);
            uint32_t bf[8][2];
#pragma unroll
            for (int p = 0; p < 4; p++) {
                int m = l >> 3;
                int row = wn * 64 + (p * 2 + (m >> 1)) * 8 + (l & 7);
                uint32_t r4[4];
                ldsm_x4(r4, sB + row * PITCH + (kk + (m & 1) * 8) * 2);
                bf[p * 2][0] = r4[0]; bf[p * 2][1] = r4[1];
                bf[p * 2 + 1][0] = r4[2]; bf[p * 2 + 1][1] = r4[3];
            }
#pragma unroll
            for (int mi = 0; mi < 2; mi++)
#pragma unroll
                for (int n = 0; n < 8; n++)
                    mma16816(c[mi][n], a2[mi], bf[n]);
        }
        __syncthreads();
    }

    // Epilogue: fp32 stores
#pragma unroll
    for (int mi = 0; mi < 2; mi++)
#pragma unroll
        for (int n = 0; n < 8; n++) {
            int row = t0 + wm * 32 + mi * 16 + (l >> 2);
            int col = h0 + wn * 64 + n * 8 + ((l & 3) << 1);
            float2 v0 = make_float2(c[mi][n][0], c[mi][n][1]);
            float2 v1 = make_float2(c[mi][n][2], c[mi][n][3]);
            *(float2*)(out + (size_t)row * H_DIM + col) = v0;
            *(float2*)(out + (size_t)(row + 8) * H_DIM + col) = v1;
        }
}

// ---------------------------------------------------------------------------
// Launch
// ---------------------------------------------------------------------------
extern "C" void kernel_launch(void* const* d_in, const int* in_sizes, int n_in,
                              void* d_out, int out_size) {
    const float* x  = (const float*)d_in[0];
    const float* wg = (const float*)d_in[1];
    const float* wu = (const float*)d_in[2];
    const float* wd = (const float*)d_in[3];
    const float* sg = (const float*)d_in[4];
    const float* su = (const float*)d_in[5];
    const float* sd = (const float*)d_in[6];
    float* out = (float*)d_out;
    (void)in_sizes; (void)n_in; (void)out_size;

    cudaFuncSetAttribute(gemm2_kernel, cudaFuncAttributeMaxDynamicSharedMemorySize,
                         G2_SMEM);

    transpose_dequant_kernel<<<dim3(I_DIM / 32, H_DIM / 32), dim3(32, 8)>>>(wd, sd);
    // T-tiles fastest (blockIdx.x) so concurrent CTAs dedup weight reads in L2
    gemm1_kernel<<<dim3(T_DIM / 128, I_DIM / 64), 256>>>(x, wg, wu, sg, su);
    gemm2_kernel<<<dim3(T_DIM / 128, H_DIM / 128), 256, G2_SMEM>>>(out);
}

// round 8
// speedup vs baseline: 1.0643x; 1.0643x over previous
#include <cuda_runtime.h>
#include <cuda_fp16.h>
#include <cstdint>

// ---------------------------------------------------------------------------
// Problem constants
// ---------------------------------------------------------------------------
#define T_DIM 512
#define H_DIM 4096
#define I_DIM 11008

#define PITCH 80                 // bytes per 32-half smem row (ldmatrix-safe)
#define NK1 (H_DIM / 32)         // 128 k-stages for gemm1
#define NK2 (I_DIM / 32)         // 344 k-stages for gemm2

#define G1_STAGE 20480           // A(10240) + Bg(5120) + Bu(5120)

// gemm2: A = g_h fp16 [128 rows][32 halfs, pitch 80] ; B = wd fp16 [32 k rows][128 h, pitch 272]
#define G2B_PITCH 272            // 17 x 16B -> conflict-free ldmatrix.trans
#define G2_A_BYTES (128 * PITCH)        // 10240
#define G2_B_BYTES (32 * G2B_PITCH)     // 8704
#define G2_STAGE (G2_A_BYTES + G2_B_BYTES)  // 18944

// Scratch (device globals — allocations are forbidden)
__device__ __align__(256) __half g_h[(size_t)T_DIM * I_DIM];   // 11.3 MB
__device__ __align__(256) __half g_x[(size_t)T_DIM * H_DIM];   // 4 MB

// ---------------------------------------------------------------------------
// sm_80-baseline PTX helpers (NO tcgen05 — harness targets compute_103 non-'a')
// ---------------------------------------------------------------------------
__device__ __forceinline__ uint32_t smem_u32(const void* p) {
    uint32_t a;
    asm("{ .reg .u64 t; cvta.to.shared.u64 t, %1; cvt.u32.u64 %0, t; }"
        : "=r"(a) : "l"(p));
    return a;
}

__device__ __forceinline__ void ldsm_x4(uint32_t* r, uint32_t addr) {
    asm volatile("ldmatrix.sync.aligned.m8n8.x4.shared.b16 {%0,%1,%2,%3}, [%4];"
                 : "=r"(r[0]), "=r"(r[1]), "=r"(r[2]), "=r"(r[3]) : "r"(addr));
}

__device__ __forceinline__ void ldsm_x4_t(uint32_t* r, uint32_t addr) {
    asm volatile("ldmatrix.sync.aligned.m8n8.x4.trans.shared.b16 {%0,%1,%2,%3}, [%4];"
                 : "=r"(r[0]), "=r"(r[1]), "=r"(r[2]), "=r"(r[3]) : "r"(addr));
}

__device__ __forceinline__ void mma16816(float* c, const uint32_t* a, const uint32_t* b) {
    asm volatile(
        "mma.sync.aligned.m16n8k16.row.col.f32.f16.f16.f32 "
        "{%0,%1,%2,%3}, {%4,%5,%6,%7}, {%8,%9}, {%0,%1,%2,%3};"
        : "+f"(c[0]), "+f"(c[1]), "+f"(c[2]), "+f"(c[3])
        : "r"(a[0]), "r"(a[1]), "r"(a[2]), "r"(a[3]), "r"(b[0]), "r"(b[1]));
}

// ---------------------------------------------------------------------------
// Kernel 0: x fp32 -> g_x fp16 (tiny streaming convert)
// ---------------------------------------------------------------------------
__global__ __launch_bounds__(256) void cvt_x_kernel(const float* __restrict__ x) {
    size_t i = (size_t)blockIdx.x * 256 + threadIdx.x;   // float4 index
    float4 v = reinterpret_cast<const float4*>(x)[i];
    __half2 h0 = __floats2half2_rn(v.x, v.y);
    __half2 h1 = __floats2half2_rn(v.z, v.w);
    uint2 w;
    w.x = *(uint32_t*)&h0; w.y = *(uint32_t*)&h1;
    reinterpret_cast<uint2*>(g_x)[i] = w;
}

// ---------------------------------------------------------------------------
// GEMM1 staging: A fp16 copy from g_x; B fp32 LDG -> fused scale+cvt -> smem
// ---------------------------------------------------------------------------
__device__ __forceinline__ void ldg_g1(const float* __restrict__ wg,
                                       const float* __restrict__ wu,
                                       int t0, int i0, int k0, int tid,
                                       uint4* a4, float4* bgv, float4* buv) {
#pragma unroll
    for (int j = 0; j < 2; j++) {
        int idx = tid + j * 256;          // 0..511 (128 rows x 4 uint4)
        int r = idx >> 2, c = idx & 3;
        a4[j] = *(const uint4*)(g_x + (size_t)(t0 + r) * H_DIM + k0 + c * 8);
    }
#pragma unroll
    for (int j = 0; j < 2; j++) {
        int idx = tid + j * 256;          // 0..511 (64 rows x 8 float4)
        int r = idx >> 3, c = idx & 7;
        bgv[j] = *(const float4*)(wg + (size_t)(i0 + r) * H_DIM + k0 + c * 4);
        buv[j] = *(const float4*)(wu + (size_t)(i0 + r) * H_DIM + k0 + c * 4);
    }
}

__device__ __forceinline__ void sts_g1(char* st, int tid, float sgv, float suv,
                                       const uint4* a4, const float4* bgv,
                                       const float4* buv) {
#pragma unroll
    for (int j = 0; j < 2; j++) {
        int idx = tid + j * 256;
        int r = idx >> 2, c = idx & 3;
        *(uint4*)(st + r * PITCH + c * 16) = a4[j];
    }
#pragma unroll
    for (int j = 0; j < 2; j++) {
        int idx = tid + j * 256;
        int r = idx >> 3, c = idx & 7;
        {
            __half2 h0 = __floats2half2_rn(bgv[j].x * sgv, bgv[j].y * sgv);
            __half2 h1 = __floats2half2_rn(bgv[j].z * sgv, bgv[j].w * sgv);
            uint2 w;
            w.x = *(uint32_t*)&h0; w.y = *(uint32_t*)&h1;
            *(uint2*)(st + 10240 + r * PITCH + c * 8) = w;
        }
        {
            __half2 h0 = __floats2half2_rn(buv[j].x * suv, buv[j].y * suv);
            __half2 h1 = __floats2half2_rn(buv[j].z * suv, buv[j].w * suv);
            uint2 w;
            w.x = *(uint32_t*)&h0; w.y = *(uint32_t*)&h1;
            *(uint2*)(st + 15360 + r * PITCH + c * 8) = w;
        }
    }
}

// ---------------------------------------------------------------------------
// Kernel 1: gate/up dual GEMM + SwiGLU -> g_h (fp16)
//   CTA: M=128 (T), N=64 (I) per matrix. 8 warps = 4(M) x 2(N). Warp: 32x32 x2.
// ---------------------------------------------------------------------------
__global__ __launch_bounds__(256, 2) void gemm1_kernel(
    const float* __restrict__ wg, const float* __restrict__ wu,
    const float* __restrict__ sg, const float* __restrict__ su) {
    __shared__ __align__(128) char sm[2 * G1_STAGE];
    const int tid = threadIdx.x, wid = tid >> 5, l = tid & 31;
    const int wm = wid & 3, wn = wid >> 2;
    const int t0 = blockIdx.x * 128, i0 = blockIdx.y * 64;
    const int iblk = i0 >> 7;
    const uint32_t sbase = smem_u32(sm);

    float cg[2][4][4], cu[2][4][4];
#pragma unroll
    for (int a = 0; a < 2; a++)
#pragma unroll
        for (int b = 0; b < 4; b++)
#pragma unroll
            for (int d = 0; d < 4; d++) { cg[a][b][d] = 0.f; cu[a][b][d] = 0.f; }

    uint4 a4[2];
    float4 bgv[2], buv[2];
    ldg_g1(wg, wu, t0, i0, 0, tid, a4, bgv, buv);
    sts_g1(sm, tid, __ldg(sg + iblk * 32), __ldg(su + iblk * 32), a4, bgv, buv);
    __syncthreads();

    for (int it = 0; it < NK1; it++) {
        float sgv = 0.f, suv = 0.f;
        if (it + 1 < NK1) {
            ldg_g1(wg, wu, t0, i0, (it + 1) * 32, tid, a4, bgv, buv);
            int kb = (it + 1) >> 2;
            sgv = __ldg(sg + iblk * 32 + kb);
            suv = __ldg(su + iblk * 32 + kb);
        }

        const uint32_t sA = sbase + (it & 1) * G1_STAGE;
        const uint32_t sBg = sA + 10240;
        const uint32_t sBu = sA + 15360;
#pragma unroll
        for (int kk = 0; kk < 32; kk += 16) {
            uint32_t a2[2][4];
#pragma unroll
            for (int mi = 0; mi < 2; mi++)
                ldsm_x4(a2[mi], sA + (wm * 32 + mi * 16 + (l & 15)) * PITCH +
                                   (kk + ((l >> 4) << 3)) * 2);
            uint32_t bg[4][2], bu[4][2];
#pragma unroll
            for (int p = 0; p < 2; p++) {
                int m = l >> 3;
                int row = wn * 32 + (p * 2 + (m >> 1)) * 8 + (l & 7);
                uint32_t aoff = row * PITCH + (kk + (m & 1) * 8) * 2;
                uint32_t r4[4];
                ldsm_x4(r4, sBg + aoff);
                bg[p * 2][0] = r4[0]; bg[p * 2][1] = r4[1];
                bg[p * 2 + 1][0] = r4[2]; bg[p * 2 + 1][1] = r4[3];
                ldsm_x4(r4, sBu + aoff);
                bu[p * 2][0] = r4[0]; bu[p * 2][1] = r4[1];
                bu[p * 2 + 1][0] = r4[2]; bu[p * 2 + 1][1] = r4[3];
            }
#pragma unroll
            for (int mi = 0; mi < 2; mi++)
#pragma unroll
                for (int n = 0; n < 4; n++) {
                    mma16816(cg[mi][n], a2[mi], bg[n]);
                    mma16816(cu[mi][n], a2[mi], bu[n]);
                }
        }

        if (it + 1 < NK1)
            sts_g1(sm + ((it + 1) & 1) * G1_STAGE, tid, sgv, suv, a4, bgv, buv);
        __syncthreads();
    }

    // Epilogue: h = silu(gate) * up -> fp16 g_h
#pragma unroll
    for (int mi = 0; mi < 2; mi++)
#pragma unroll
        for (int n = 0; n < 4; n++) {
            int row = t0 + wm * 32 + mi * 16 + (l >> 2);
            int col = i0 + wn * 32 + n * 8 + ((l & 3) << 1);
            {
                float g0 = cg[mi][n][0], g1 = cg[mi][n][1];
                float h0 = g0 * cu[mi][n][0] / (1.0f + __expf(-g0));
                float h1 = g1 * cu[mi][n][1] / (1.0f + __expf(-g1));
                __half2 hv = __floats2half2_rn(h0, h1);
                *(uint32_t*)(&g_h[(size_t)row * I_DIM + col]) = *(uint32_t*)&hv;
            }
            {
                float g0 = cg[mi][n][2], g1 = cg[mi][n][3];
                float h0 = g0 * cu[mi][n][2] / (1.0f + __expf(-g0));
                float h1 = g1 * cu[mi][n][3] / (1.0f + __expf(-g1));
                __half2 hv = __floats2half2_rn(h0, h1);
                *(uint32_t*)(&g_h[(size_t)(row + 8) * I_DIM + col]) = *(uint32_t*)&hv;
            }
        }
}

// ---------------------------------------------------------------------------
// GEMM2 staging: A fp16 copy from g_h; B = wd fp32 [K=32][N=128] tile,
// fused dequant-scale + cvt into h-contiguous smem (ldmatrix.trans source)
// ---------------------------------------------------------------------------
__device__ __forceinline__ void ldg_g2(const float* __restrict__ wd,
                                       int t0, int h0, int k0, int tid,
                                       uint4* a4, float4* b4) {
#pragma unroll
    for (int j = 0; j < 2; j++) {
        int idx = tid + j * 256;          // 128 rows x 4 uint4
        int r = idx >> 2, c = idx & 3;
        a4[j] = *(const uint4*)(g_h + (size_t)(t0 + r) * I_DIM + k0 + c * 8);
    }
#pragma unroll
    for (int j = 0; j < 4; j++) {
        int f = tid + j * 256;            // 32 rows x 32 float4
        int r = f >> 5, c4 = f & 31;
        b4[j] = *(const float4*)(wd + (size_t)(k0 + r) * H_DIM + h0 + c4 * 4);
    }
}

__device__ __forceinline__ void sts_g2(char* st, int tid, float s,
                                       const uint4* a4, const float4* b4) {
#pragma unroll
    for (int j = 0; j < 2; j++) {
        int idx = tid + j * 256;
        int r = idx >> 2, c = idx & 3;
        *(uint4*)(st + r * PITCH + c * 16) = a4[j];
    }
#pragma unroll
    for (int j = 0; j < 4; j++) {
        int f = tid + j * 256;
        int r = f >> 5, c4 = f & 31;
        __half2 h0 = __floats2half2_rn(b4[j].x * s, b4[j].y * s);
        __half2 h1 = __floats2half2_rn(b4[j].z * s, b4[j].w * s);
        uint2 w;
        w.x = *(uint32_t*)&h0; w.y = *(uint32_t*)&h1;
        *(uint2*)(st + G2_A_BYTES + r * G2B_PITCH + c4 * 8) = w;
    }
}

// ---------------------------------------------------------------------------
// Kernel 2: out[T,H] = g_h[T,I] x dequant(Wd)[I,H]  (fp16 mma, fp32 out)
//   CTA: 128x128, BK=32, register double-buffer. Warp tile 32x64.
//   B frags via ldmatrix.x4.trans from [k][h] tile.
// ---------------------------------------------------------------------------
__global__ __launch_bounds__(256, 2) void gemm2_kernel(
    const float* __restrict__ wd, const float* __restrict__ sd,
    float* __restrict__ out) {
    __shared__ __align__(128) char sm2[2 * G2_STAGE];
    const int tid = threadIdx.x, wid = tid >> 5, l = tid & 31;
    const int wm = wid & 3, wn = wid >> 2;
    const int t0 = blockIdx.x * 128, h0 = blockIdx.y * 128;
    const int hb = h0 >> 7;
    const uint32_t sbase = smem_u32(sm2);

    float c[2][8][4];
#pragma unroll
    for (int a = 0; a < 2; a++)
#pragma unroll
        for (int b = 0; b < 8; b++)
#pragma unroll
            for (int d = 0; d < 4; d++) c[a][b][d] = 0.f;

    uint4 a4[2];
    float4 b4[4];
    ldg_g2(wd, t0, h0, 0, tid, a4, b4);
    sts_g2(sm2, tid, __ldg(sd + hb), a4, b4);
    __syncthreads();

    for (int it = 0; it < NK2; it++) {
        float sv = 0.f;
        if (it + 1 < NK2) {
            ldg_g2(wd, t0, h0, (it + 1) * 32, tid, a4, b4);
            sv = __ldg(sd + ((it + 1) >> 2) * (H_DIM / 128) + hb);
        }

        const uint32_t sA = sbase + (it & 1) * G2_STAGE;
        const uint32_t sB = sA + G2_A_BYTES;
#pragma unroll
        for (int kk = 0; kk < 32; kk += 16) {
            uint32_t a2[2][4];
#pragma unroll
            for (int mi = 0; mi < 2; mi++)
                ldsm_x4(a2[mi], sA + (wm * 32 + mi * 16 + (l & 15)) * PITCH +
                                   (kk + ((l >> 4) << 3)) * 2);
            uint32_t bf[8][2];
#pragma unroll
            for (int p = 0; p < 4; p++) {
                // ldmatrix.trans of [k][h] tile: tiles (t&1)=k-half, (t>>1)=n-half
                int t = l >> 3, rr = l & 7;
                uint32_t baddr = sB + (kk + (t & 1) * 8 + rr) * G2B_PITCH +
                                 (wn * 64 + p * 16 + (t >> 1) * 8) * 2;
                uint32_t r4[4];
                ldsm_x4_t(r4, baddr);
                bf[p * 2][0] = r4[0]; bf[p * 2][1] = r4[1];
                bf[p * 2 + 1][0] = r4[2]; bf[p * 2 + 1][1] = r4[3];
            }
#pragma unroll
            for (int mi = 0; mi < 2; mi++)
#pragma unroll
                for (int n = 0; n < 8; n++)
                    mma16816(c[mi][n], a2[mi], bf[n]);
        }

        if (it + 1 < NK2)
            sts_g2(sm2 + ((it + 1) & 1) * G2_STAGE, tid, sv, a4, b4);
        __syncthreads();
    }

    // Epilogue: fp32 stores
#pragma unroll
    for (int mi = 0; mi < 2; mi++)
#pragma unroll
        for (int n = 0; n < 8; n++) {
            int row = t0 + wm * 32 + mi * 16 + (l >> 2);
            int col = h0 + wn * 64 + n * 8 + ((l & 3) << 1);
            float2 v0 = make_float2(c[mi][n][0], c[mi][n][1]);
            float2 v1 = make_float2(c[mi][n][2], c[mi][n][3]);
            *(float2*)(out + (size_t)row * H_DIM + col) = v0;
            *(float2*)(out + (size_t)(row + 8) * H_DIM + col) = v1;
        }
}

// ---------------------------------------------------------------------------
// Launch
// ---------------------------------------------------------------------------
extern "C" void kernel_launch(void* const* d_in, const int* in_sizes, int n_in,
                              void* d_out, int out_size) {
    const float* x  = (const float*)d_in[0];
    const float* wg = (const float*)d_in[1];
    const float* wu = (const float*)d_in[2];
    const float* wd = (const float*)d_in[3];
    const float* sg = (const float*)d_in[4];
    const float* su = (const float*)d_in[5];
    const float* sd = (const float*)d_in[6];
    float* out = (float*)d_out;
    (void)in_sizes; (void)n_in; (void)out_size;

    cvt_x_kernel<<<(T_DIM * H_DIM / 4) / 256, 256>>>(x);
    // T-tiles fastest (blockIdx.x) so concurrent CTAs dedup weight reads in L2
    gemm1_kernel<<<dim3(T_DIM / 128, I_DIM / 64), 256>>>(wg, wu, sg, su);
    gemm2_kernel<<<dim3(T_DIM / 128, H_DIM / 128), 256>>>(wd, sd, out);
}

// round 9
// speedup vs baseline: 1.2249x; 1.1509x over previous
#include <cuda_runtime.h>
#include <cuda_fp16.h>
#include <cstdint>

// ---------------------------------------------------------------------------
// Problem constants
// ---------------------------------------------------------------------------
#define T_DIM 512
#define H_DIM 4096
#define I_DIM 11008

#define PITCH 80                 // gemm1: bytes per 32-half smem row
#define NK1 (H_DIM / 32)         // 128 k-stages for gemm1 (BK=32)
#define NK2 (I_DIM / 64)         // 172 k-stages for gemm2 (BK=64)

#define G1_STAGE 20480           // A(10240) + Bg(5120) + Bu(5120)

// gemm2: tile M=128, N=64, BK=64. pitch 144 = 9x16B (conflict-free ldmatrix)
#define G2_PITCH 144
#define G2_A_BYTES (128 * G2_PITCH)     // 18432 : A [128 t][64 k halfs]
#define G2_B_BYTES (64 * G2_PITCH)      // 9216  : B [64 k][64 h halfs]
#define G2_STAGE (G2_A_BYTES + G2_B_BYTES)  // 27648
#define G2_SMEM (2 * G2_STAGE)              // 55296 (dynamic)

// Scratch (device globals — allocations are forbidden)
__device__ __align__(256) __half g_h[(size_t)T_DIM * I_DIM];   // 11.3 MB
__device__ __align__(256) __half g_x[(size_t)T_DIM * H_DIM];   // 4 MB

// ---------------------------------------------------------------------------
// sm_80-baseline PTX helpers (NO tcgen05 — harness targets compute_103 non-'a')
// ---------------------------------------------------------------------------
__device__ __forceinline__ uint32_t smem_u32(const void* p) {
    uint32_t a;
    asm("{ .reg .u64 t; cvta.to.shared.u64 t, %1; cvt.u32.u64 %0, t; }"
        : "=r"(a) : "l"(p));
    return a;
}

__device__ __forceinline__ void ldsm_x4(uint32_t* r, uint32_t addr) {
    asm volatile("ldmatrix.sync.aligned.m8n8.x4.shared.b16 {%0,%1,%2,%3}, [%4];"
                 : "=r"(r[0]), "=r"(r[1]), "=r"(r[2]), "=r"(r[3]) : "r"(addr));
}

__device__ __forceinline__ void ldsm_x4_t(uint32_t* r, uint32_t addr) {
    asm volatile("ldmatrix.sync.aligned.m8n8.x4.trans.shared.b16 {%0,%1,%2,%3}, [%4];"
                 : "=r"(r[0]), "=r"(r[1]), "=r"(r[2]), "=r"(r[3]) : "r"(addr));
}

__device__ __forceinline__ void mma16816(float* c, const uint32_t* a, const uint32_t* b) {
    asm volatile(
        "mma.sync.aligned.m16n8k16.row.col.f32.f16.f16.f32 "
        "{%0,%1,%2,%3}, {%4,%5,%6,%7}, {%8,%9}, {%0,%1,%2,%3};"
        : "+f"(c[0]), "+f"(c[1]), "+f"(c[2]), "+f"(c[3])
        : "r"(a[0]), "r"(a[1]), "r"(a[2]), "r"(a[3]), "r"(b[0]), "r"(b[1]));
}

__device__ __forceinline__ void cp16(uint32_t sdst, const void* gsrc) {
    asm volatile("cp.async.cg.shared.global [%0], [%1], 16;"
                 :: "r"(sdst), "l"(__cvta_generic_to_global(gsrc)));
}
#define CP_COMMIT() asm volatile("cp.async.commit_group;")
#define CP_WAIT0()  asm volatile("cp.async.wait_group 0;")

// ---------------------------------------------------------------------------
// Kernel 0: x fp32 -> g_x fp16 (tiny streaming convert)
// ---------------------------------------------------------------------------
__global__ __launch_bounds__(256) void cvt_x_kernel(const float* __restrict__ x) {
    size_t i = (size_t)blockIdx.x * 256 + threadIdx.x;   // float4 index
    float4 v = reinterpret_cast<const float4*>(x)[i];
    __half2 h0 = __floats2half2_rn(v.x, v.y);
    __half2 h1 = __floats2half2_rn(v.z, v.w);
    uint2 w;
    w.x = *(uint32_t*)&h0; w.y = *(uint32_t*)&h1;
    reinterpret_cast<uint2*>(g_x)[i] = w;
}

// ---------------------------------------------------------------------------
// GEMM1 staging
// ---------------------------------------------------------------------------
__device__ __forceinline__ void cp_a_g1(uint32_t sA, int t0, int k0, int tid) {
#pragma unroll
    for (int j = 0; j < 2; j++) {            // 128 rows x 4 chunks (16B)
        int idx = tid + j * 256;
        int r = idx >> 2, c = idx & 3;
        cp16(sA + r * PITCH + c * 16, g_x + (size_t)(t0 + r) * H_DIM + k0 + c * 8);
    }
    CP_COMMIT();
}

__device__ __forceinline__ void ldg_b_g1(const float* __restrict__ wg,
                                         const float* __restrict__ wu,
                                         int i0, int k0, int tid,
                                         float4* bgv, float4* buv) {
#pragma unroll
    for (int j = 0; j < 2; j++) {            // 64 rows x 8 float4
        int idx = tid + j * 256;
        int r = idx >> 3, c = idx & 7;
        bgv[j] = *(const float4*)(wg + (size_t)(i0 + r) * H_DIM + k0 + c * 4);
        buv[j] = *(const float4*)(wu + (size_t)(i0 + r) * H_DIM + k0 + c * 4);
    }
}

__device__ __forceinline__ void sts_b_g1(char* st, int tid, float sgv, float suv,
                                         const float4* bgv, const float4* buv) {
#pragma unroll
    for (int j = 0; j < 2; j++) {
        int idx = tid + j * 256;
        int r = idx >> 3, c = idx & 7;
        {
            __half2 h0 = __floats2half2_rn(bgv[j].x * sgv, bgv[j].y * sgv);
            __half2 h1 = __floats2half2_rn(bgv[j].z * sgv, bgv[j].w * sgv);
            uint2 w;
            w.x = *(uint32_t*)&h0; w.y = *(uint32_t*)&h1;
            *(uint2*)(st + 10240 + r * PITCH + c * 8) = w;
        }
        {
            __half2 h0 = __floats2half2_rn(buv[j].x * suv, buv[j].y * suv);
            __half2 h1 = __floats2half2_rn(buv[j].z * suv, buv[j].w * suv);
            uint2 w;
            w.x = *(uint32_t*)&h0; w.y = *(uint32_t*)&h1;
            *(uint2*)(st + 15360 + r * PITCH + c * 8) = w;
        }
    }
}

// ---------------------------------------------------------------------------
// Kernel 1: gate/up dual GEMM + SwiGLU -> g_h (fp16)
//   CTA: M=128 (T), N=64 (I) per matrix. 8 warps = 4(M) x 2(N). Warp: 32x32 x2.
//   A via cp.async from g_x; B via reg-buffered LDG + fused dequant-cvt.
// ---------------------------------------------------------------------------
__global__ __launch_bounds__(256, 2) void gemm1_kernel(
    const float* __restrict__ wg, const float* __restrict__ wu,
    const float* __restrict__ sg, const float* __restrict__ su) {
    __shared__ __align__(128) char sm[2 * G1_STAGE];
    const int tid = threadIdx.x, wid = tid >> 5, l = tid & 31;
    const int wm = wid & 3, wn = wid >> 2;
    const int t0 = blockIdx.x * 128, i0 = blockIdx.y * 64;
    const int iblk = i0 >> 7;
    const uint32_t sbase = smem_u32(sm);

    float cg[2][4][4], cu[2][4][4];
#pragma unroll
    for (int a = 0; a < 2; a++)
#pragma unroll
        for (int b = 0; b < 4; b++)
#pragma unroll
            for (int d = 0; d < 4; d++) { cg[a][b][d] = 0.f; cu[a][b][d] = 0.f; }

    float4 bgv[2], buv[2];
    cp_a_g1(sbase, t0, 0, tid);
    ldg_b_g1(wg, wu, i0, 0, tid, bgv, buv);
    sts_b_g1(sm, tid, __ldg(sg + iblk * 32), __ldg(su + iblk * 32), bgv, buv);
    CP_WAIT0();
    __syncthreads();

    for (int it = 0; it < NK1; it++) {
        float sgv = 0.f, suv = 0.f;
        if (it + 1 < NK1) {
            cp_a_g1(sbase + ((it + 1) & 1) * G1_STAGE, t0, (it + 1) * 32, tid);
            ldg_b_g1(wg, wu, i0, (it + 1) * 32, tid, bgv, buv);
            int kb = (it + 1) >> 2;
            sgv = __ldg(sg + iblk * 32 + kb);
            suv = __ldg(su + iblk * 32 + kb);
        }

        const uint32_t sA = sbase + (it & 1) * G1_STAGE;
        const uint32_t sBg = sA + 10240;
        const uint32_t sBu = sA + 15360;
#pragma unroll
        for (int kk = 0; kk < 32; kk += 16) {
            uint32_t a2[2][4];
#pragma unroll
            for (int mi = 0; mi < 2; mi++)
                ldsm_x4(a2[mi], sA + (wm * 32 + mi * 16 + (l & 15)) * PITCH +
                                   (kk + ((l >> 4) << 3)) * 2);
            uint32_t bg[4][2], bu[4][2];
#pragma unroll
            for (int p = 0; p < 2; p++) {
                int m = l >> 3;
                int row = wn * 32 + (p * 2 + (m >> 1)) * 8 + (l & 7);
                uint32_t aoff = row * PITCH + (kk + (m & 1) * 8) * 2;
                uint32_t r4[4];
                ldsm_x4(r4, sBg + aoff);
                bg[p * 2][0] = r4[0]; bg[p * 2][1] = r4[1];
                bg[p * 2 + 1][0] = r4[2]; bg[p * 2 + 1][1] = r4[3];
                ldsm_x4(r4, sBu + aoff);
                bu[p * 2][0] = r4[0]; bu[p * 2][1] = r4[1];
                bu[p * 2 + 1][0] = r4[2]; bu[p * 2 + 1][1] = r4[3];
            }
#pragma unroll
            for (int mi = 0; mi < 2; mi++)
#pragma unroll
                for (int n = 0; n < 4; n++) {
                    mma16816(cg[mi][n], a2[mi], bg[n]);
                    mma16816(cu[mi][n], a2[mi], bu[n]);
                }
        }

        if (it + 1 < NK1) {
            sts_b_g1(sm + ((it + 1) & 1) * G1_STAGE, tid, sgv, suv, bgv, buv);
            CP_WAIT0();
        }
        __syncthreads();
    }

    // Epilogue: h = silu(gate) * up -> fp16 g_h
#pragma unroll
    for (int mi = 0; mi < 2; mi++)
#pragma unroll
        for (int n = 0; n < 4; n++) {
            int row = t0 + wm * 32 + mi * 16 + (l >> 2);
            int col = i0 + wn * 32 + n * 8 + ((l & 3) << 1);
            {
                float g0 = cg[mi][n][0], g1 = cg[mi][n][1];
                float h0 = g0 * cu[mi][n][0] / (1.0f + __expf(-g0));
                float h1 = g1 * cu[mi][n][1] / (1.0f + __expf(-g1));
                __half2 hv = __floats2half2_rn(h0, h1);
                *(uint32_t*)(&g_h[(size_t)row * I_DIM + col]) = *(uint32_t*)&hv;
            }
            {
                float g0 = cg[mi][n][2], g1 = cg[mi][n][3];
                float h0 = g0 * cu[mi][n][2] / (1.0f + __expf(-g0));
                float h1 = g1 * cu[mi][n][3] / (1.0f + __expf(-g1));
                __half2 hv = __floats2half2_rn(h0, h1);
                *(uint32_t*)(&g_h[(size_t)(row + 8) * I_DIM + col]) = *(uint32_t*)&hv;
            }
        }
}

// ---------------------------------------------------------------------------
// GEMM2 staging (tile 128x64, BK=64)
// ---------------------------------------------------------------------------
__device__ __forceinline__ void cp_a_g2(uint32_t sA, int t0, int k0, int tid) {
#pragma unroll
    for (int j = 0; j < 4; j++) {            // 128 rows x 8 chunks (16B)
        int idx = tid + j * 256;
        int r = idx >> 3, c = idx & 7;
        cp16(sA + r * G2_PITCH + c * 16, g_h + (size_t)(t0 + r) * I_DIM + k0 + c * 8);
    }
    CP_COMMIT();
}

__device__ __forceinline__ void ldg_b_g2(const float* __restrict__ wd,
                                         int h0, int k0, int tid, float4* b4) {
#pragma unroll
    for (int j = 0; j < 4; j++) {            // 64 k-rows x 16 float4
        int idx = tid + j * 256;
        int r = idx >> 4, c4 = idx & 15;
        b4[j] = *(const float4*)(wd + (size_t)(k0 + r) * H_DIM + h0 + c4 * 4);
    }
}

__device__ __forceinline__ void sts_b_g2(char* st, int tid, float s, const float4* b4) {
#pragma unroll
    for (int j = 0; j < 4; j++) {
        int idx = tid + j * 256;
        int r = idx >> 4, c4 = idx & 15;
        __half2 h0 = __floats2half2_rn(b4[j].x * s, b4[j].y * s);
        __half2 h1 = __floats2half2_rn(b4[j].z * s, b4[j].w * s);
        uint2 w;
        w.x = *(uint32_t*)&h0; w.y = *(uint32_t*)&h1;
        *(uint2*)(st + G2_A_BYTES + r * G2_PITCH + c4 * 8) = w;
    }
}

// ---------------------------------------------------------------------------
// Kernel 2: out[T,H] = g_h[T,I] x dequant(Wd)[I,H]  (fp16 mma, fp32 out)
//   CTA: 128x64, BK=64. 8 warps = 4(M) x 2(N). Warp tile 32x32.
//   A via cp.async; B via reg-buffered LDG + fused dequant-cvt;
//   B frags via ldmatrix.x4.trans from [k][h] tile.
// ---------------------------------------------------------------------------
__global__ __launch_bounds__(256, 2) void gemm2_kernel(
    const float* __restrict__ wd, const float* __restrict__ sd,
    float* __restrict__ out) {
    extern __shared__ __align__(128) char sm2[];
    const int tid = threadIdx.x, wid = tid >> 5, l = tid & 31;
    const int wm = wid & 3, wn = wid >> 2;
    const int t0 = blockIdx.x * 128, h0 = blockIdx.y * 64;
    const int hb = h0 >> 7;
    const uint32_t sbase = smem_u32(sm2);

    float c[2][4][4];
#pragma unroll
    for (int a = 0; a < 2; a++)
#pragma unroll
        for (int b = 0; b < 4; b++)
#pragma unroll
            for (int d = 0; d < 4; d++) c[a][b][d] = 0.f;

    float4 b4[4];
    cp_a_g2(sbase, t0, 0, tid);
    ldg_b_g2(wd, h0, 0, tid, b4);
    sts_b_g2(sm2, tid, __ldg(sd + hb), b4);
    CP_WAIT0();
    __syncthreads();

    for (int it = 0; it < NK2; it++) {
        float sv = 0.f;
        if (it + 1 < NK2) {
            cp_a_g2(sbase + ((it + 1) & 1) * G2_STAGE, t0, (it + 1) * 64, tid);
            ldg_b_g2(wd, h0, (it + 1) * 64, tid, b4);
            sv = __ldg(sd + ((it + 1) >> 1) * (H_DIM / 128) + hb);
        }

        const uint32_t sA = sbase + (it & 1) * G2_STAGE;
        const uint32_t sB = sA + G2_A_BYTES;
#pragma unroll
        for (int kk = 0; kk < 64; kk += 16) {
            uint32_t a2[2][4];
#pragma unroll
            for (int mi = 0; mi < 2; mi++)
                ldsm_x4(a2[mi], sA + (wm * 32 + mi * 16 + (l & 15)) * G2_PITCH +
                                   (kk + ((l >> 4) << 3)) * 2);
            uint32_t bf[4][2];
#pragma unroll
            for (int p = 0; p < 2; p++) {
                // ldmatrix.trans of [k][h] tile: (t&1)=k-half, (t>>1)=n-half
                int t = l >> 3, rr = l & 7;
                uint32_t baddr = sB + (kk + (t & 1) * 8 + rr) * G2_PITCH +
                                 (wn * 32 + p * 16 + (t >> 1) * 8) * 2;
                uint32_t r4[4];
                ldsm_x4_t(r4, baddr);
                bf[p * 2][0] = r4[0]; bf[p * 2][1] = r4[1];
                bf[p * 2 + 1][0] = r4[2]; bf[p * 2 + 1][1] = r4[3];
            }
#pragma unroll
            for (int mi = 0; mi < 2; mi++)
#pragma unroll
                for (int n = 0; n < 4; n++)
                    mma16816(c[mi][n], a2[mi], bf[n]);
        }

        if (it + 1 < NK2) {
            sts_b_g2(sm2 + ((it + 1) & 1) * G2_STAGE, tid, sv, b4);
            CP_WAIT0();
        }
        __syncthreads();
    }

    // Epilogue: fp32 stores
#pragma unroll
    for (int mi = 0; mi < 2; mi++)
#pragma unroll
        for (int n = 0; n < 4; n++) {
            int row = t0 + wm * 32 + mi * 16 + (l >> 2);
            int col = h0 + wn * 32 + n * 8 + ((l & 3) << 1);
            float2 v0 = make_float2(c[mi][n][0], c[mi][n][1]);
            float2 v1 = make_float2(c[mi][n][2], c[mi][n][3]);
            *(float2*)(out + (size_t)row * H_DIM + col) = v0;
            *(float2*)(out + (size_t)(row + 8) * H_DIM + col) = v1;
        }
}

// ---------------------------------------------------------------------------
// Launch
// ---------------------------------------------------------------------------
extern "C" void kernel_launch(void* const* d_in, const int* in_sizes, int n_in,
                              void* d_out, int out_size) {
    const float* x  = (const float*)d_in[0];
    const float* wg = (const float*)d_in[1];
    const float* wu = (const float*)d_in[2];
    const float* wd = (const float*)d_in[3];
    const float* sg = (const float*)d_in[4];
    const float* su = (const float*)d_in[5];
    const float* sd = (const float*)d_in[6];
    float* out = (float*)d_out;
    (void)in_sizes; (void)n_in; (void)out_size;

    cudaFuncSetAttribute(gemm2_kernel, cudaFuncAttributeMaxDynamicSharedMemorySize,
                         G2_SMEM);

    cvt_x_kernel<<<(T_DIM * H_DIM / 4) / 256, 256>>>(x);
    // T-tiles fastest (blockIdx.x) so concurrent CTAs dedup weight reads in L2
    gemm1_kernel<<<dim3(T_DIM / 128, I_DIM / 64), 256>>>(wg, wu, sg, su);
    gemm2_kernel<<<dim3(T_DIM / 128, H_DIM / 64), 256, G2_SMEM>>>(wd, sd, out);
}